// round 13
// baseline (speedup 1.0000x reference)
#include <cuda_runtime.h>
#include <cuda_fp16.h>
#include <math.h>
#include <stdint.h>

#define NB 16
#define NS 2048
#define NH 128
#define ND 64
#define CB 8          // batches per chunk
#define ECH ((size_t)CB * NS * NS)

typedef unsigned long long u64;

// ---------------- scratch (device globals; no allocation allowed) ----------------
__device__ float g_pe[NS * NH];
__device__ __half g_Qh[NB * NS * ND];           // fp16 Q
__device__ __half g_Kh[NB * NS * ND];           // fp16 K
__device__ float g_wvf[NH];
__device__ float g_u[NB * NS];
__device__ float g_Z[NB * NS];
__device__ float g_w[NB * NS];
// E in FRAGMENT-BLOCKED layout, double-buffered by chunk (134 MB total):
// uint2 index = ((((qt)*16+kt)*8 + warp)*16 + mi*8+j)*32 + lane  per (buf, zb)
__device__ __half g_E[2 * ECH];

// ---------------- helpers ---------------------------------------------------------
__device__ __forceinline__ uint32_t smem_u32(const void* p) {
    uint32_t a;
    asm("{ .reg .u64 t; cvta.to.shared.u64 t, %1; cvt.u32.u64 %0, t; }" : "=r"(a) : "l"(p));
    return a;
}
__device__ __forceinline__ void ldm_x4(uint32_t* r, uint32_t addr) {
    asm volatile("ldmatrix.sync.aligned.m8n8.x4.shared.b16 {%0,%1,%2,%3}, [%4];"
                 : "=r"(r[0]), "=r"(r[1]), "=r"(r[2]), "=r"(r[3]) : "r"(addr));
}
__device__ __forceinline__ void mma_f16(float* c, const uint32_t* a,
                                        uint32_t b0, uint32_t b1) {
    asm volatile(
        "mma.sync.aligned.m16n8k16.row.col.f32.f16.f16.f32 "
        "{%0,%1,%2,%3}, {%4,%5,%6,%7}, {%8,%9}, {%0,%1,%2,%3};"
        : "+f"(c[0]), "+f"(c[1]), "+f"(c[2]), "+f"(c[3])
        : "r"(a[0]), "r"(a[1]), "r"(a[2]), "r"(a[3]), "r"(b0), "r"(b1));
}
__device__ __forceinline__ float ex2f(float v) {
    float r; asm("ex2.approx.ftz.f32 %0, %1;" : "=f"(r) : "f"(v)); return r;
}
__device__ __forceinline__ u64 pack2(float lo, float hi) {
    u64 r; asm("mov.b64 %0, {%1,%2};" : "=l"(r) : "f"(lo), "f"(hi)); return r;
}
__device__ __forceinline__ void fma2(u64& c, u64 a, u64 b) {
    asm("fma.rn.f32x2 %0, %1, %2, %0;" : "+l"(c) : "l"(a), "l"(b));
}
__device__ __forceinline__ float2 unpack2(u64 v) {
    float lo, hi; asm("mov.b64 {%0,%1}, %2;" : "=f"(lo), "=f"(hi) : "l"(v));
    return make_float2(lo, hi);
}

// ---------------- kernel 1: sinusoidal PE + wvf (merged) --------------------------
__global__ void k_pewvf(const float* __restrict__ Wv, const float* __restrict__ Wf) {
    int t = threadIdx.x;
    int p = blockIdx.x * 4 + (t >> 6);
    int i = t & 63;
    double inv_rate = exp2(-(double)i * 0.20762050593046016);  // 10000^(-i/64)
    double ang = (double)p * inv_rate;
    double k = rint(ang * 0.15915494309189535);
    double r = fma(-k, 6.283185307179586, ang);
    r = fma(-k, 2.4492935982947064e-16, r);
    float s, c;
    sincosf((float)r, &s, &c);
    g_pe[p * NH + 2 * i]     = s;
    g_pe[p * NH + 2 * i + 1] = c;

    if (blockIdx.x == 0 && t < 128) {
        float sum = 0.f;
        #pragma unroll 8
        for (int d = 0; d < ND; d++) sum += Wv[t * ND + d] * Wf[d];
        g_wvf[t] = sum;
    }
}

// ---------------- kernel 2: fused xp=x+pe -> {Q,K} fp16 (HMMA) + u + Z=0 ----------
__global__ __launch_bounds__(512, 2) void k_qk(const float* __restrict__ x,
                                               const float* __restrict__ Wq,
                                               const float* __restrict__ Wk) {
    extern __shared__ __align__(16) char qs[];
    char* XPs = qs;             // [128 rows][256 B]
    char* Ws  = qs + 32768;     // [128 n][256 B]
    int t = threadIdx.x;
    int w = t >> 5, lane = t & 31;
    int r0 = blockIdx.x * 128;
    int s0 = r0 & (NS - 1);

    int zi = blockIdx.x * 512 + t;          // zero Z, bounds-guarded
    if (zi < NB * NS) g_Z[zi] = 0.f;

    // stage W transposed to [n][k] fp16
    #pragma unroll
    for (int i = 0; i < 4; i++) {
        int id = t + i * 512;
        int n = id & 127, o = id >> 7;
        const float* src = (n < 64) ? (Wq + n) : (Wk + (n - 64));
        float v0 = src[(8 * o + 0) * 64], v1 = src[(8 * o + 1) * 64];
        float v2 = src[(8 * o + 2) * 64], v3 = src[(8 * o + 3) * 64];
        float v4 = src[(8 * o + 4) * 64], v5 = src[(8 * o + 5) * 64];
        float v6 = src[(8 * o + 6) * 64], v7 = src[(8 * o + 7) * 64];
        __half2 h0 = __floats2half2_rn(v0, v1);
        __half2 h1 = __floats2half2_rn(v2, v3);
        __half2 h2 = __floats2half2_rn(v4, v5);
        __half2 h3 = __floats2half2_rn(v6, v7);
        int chunk = o ^ (n & 7);
        *(uint4*)(Ws + n * 256 + chunk * 16) =
            make_uint4(*(uint32_t*)&h0, *(uint32_t*)&h1, *(uint32_t*)&h2, *(uint32_t*)&h3);
    }

    // stage XP (fp16) + u (fp32)
    float4 wv = ((const float4*)g_wvf)[lane];
    #pragma unroll
    for (int i = 0; i < 8; i++) {
        int row = w + 16 * i;
        float4 xv = ((const float4*)(x    + (size_t)(r0 + row) * NH))[lane];
        float4 pv = ((const float4*)(g_pe + (size_t)(s0 + row) * NH))[lane];
        float xpx = xv.x + pv.x, xpy = xv.y + pv.y;
        float xpz = xv.z + pv.z, xpw = xv.w + pv.w;
        float up = xpx * wv.x + xpy * wv.y + xpz * wv.z + xpw * wv.w;
        #pragma unroll
        for (int off = 16; off; off >>= 1) up += __shfl_down_sync(0xffffffffu, up, off);
        if (lane == 0) g_u[r0 + row] = up;
        __half2 hA = __floats2half2_rn(xpx, xpy);
        __half2 hB = __floats2half2_rn(xpz, xpw);
        int chunk = (lane >> 1) ^ (row & 7);
        *(uint2*)(XPs + row * 256 + chunk * 16 + (lane & 1) * 8) =
            make_uint2(*(uint32_t*)&hA, *(uint32_t*)&hB);
    }
    __syncthreads();

    // mma: 16 warps = 8 warp_m x 2 warp_n; warp tile 16 rows x 64 cols
    int warp_m = w >> 1, warp_n = w & 1;
    int m0 = warp_m * 16, nb0 = warp_n * 64;
    int lr = lane & 15, lch = lane >> 4;

    uint32_t aXP = smem_u32(XPs), aW = smem_u32(Ws);
    float acc[8][4] = {};
    #pragma unroll
    for (int ks = 0; ks < 8; ks++) {
        uint32_t a[4];
        int rowA = m0 + lr;
        ldm_x4(a, aXP + rowA * 256 + (((2 * ks + lch) ^ (rowA & 7)) << 4));
        #pragma unroll
        for (int nb = 0; nb < 4; nb++) {
            int rowB = nb0 + nb * 16 + lr;
            uint32_t bk[4];
            ldm_x4(bk, aW + rowB * 256 + (((2 * ks + lch) ^ (rowB & 7)) << 4));
            mma_f16(acc[2 * nb],     a, bk[0], bk[2]);
            mma_f16(acc[2 * nb + 1], a, bk[1], bk[3]);
        }
    }

    int g = lane >> 2, tq = lane & 3;
    __half* base = warp_n ? g_Kh : g_Qh;
    #pragma unroll
    for (int mi = 0; mi < 2; mi++) {
        __half* drow = base + (size_t)(r0 + m0 + 8 * mi + g) * ND;
        #pragma unroll
        for (int nb = 0; nb < 4; nb++) {
            #pragma unroll
            for (int jj = 0; jj < 2; jj++) {
                int col = nb * 16 + jj * 8 + 2 * tq;
                __half2 hv = __floats2half2_rn(acc[2 * nb + jj][2 * mi],
                                               acc[2 * nb + jj][2 * mi + 1]);
                *(uint32_t*)(drow + col) = *(uint32_t*)&hv;
            }
        }
    }
}

// ---------------- kernel 3: E = exp(QK^T/8)/16 -> fragment-blocked gmem -----------
__global__ __launch_bounds__(256, 2) void k_scores(int b0, int buf) {
    extern __shared__ __align__(16) __half smh[];
    const int PITCH = 72;
    __half* QH = smh;                     // [128][72]
    __half* KH = smh + 128 * PITCH;

    int t = threadIdx.x;
    int w = t >> 5, lane = t & 31;
    int zb = blockIdx.z;                  // 0..CB-1 (E index)
    int b = b0 + zb;                      // global batch
    int qt = blockIdx.y;
    int kt = blockIdx.x;
    int k0 = kt * 128;

    const uint4* Qg = (const uint4*)(g_Qh + ((size_t)b * NS + qt * 128) * ND);
    const uint4* Kg = (const uint4*)(g_Kh + ((size_t)b * NS + k0) * ND);
    #pragma unroll
    for (int i = 0; i < 4; i++) {
        int e = t + i * 256;
        int r = e >> 3, c8 = e & 7;
        int off = r * PITCH + c8 * 8;
        *(uint4*)(QH + off) = Qg[e];
        *(uint4*)(KH + off) = Kg[e];
    }
    __syncthreads();

    int warp_m = w & 3, warp_n = w >> 2;
    int m0 = warp_m * 32, n0 = warp_n * 64;
    int lr = lane & 15;
    int lc = (lane >> 4) << 3;

    uint32_t aQH = smem_u32(QH), aKH = smem_u32(KH);
    float acc[2][8][4] = {};

    #pragma unroll
    for (int ks = 0; ks < 4; ks++) {
        int col = ks * 16 + lc;
        uint32_t a0[4], a1[4];
        ldm_x4(a0, aQH + ((m0 + lr) * PITCH + col) * 2);
        ldm_x4(a1, aQH + ((m0 + 16 + lr) * PITCH + col) * 2);
        #pragma unroll
        for (int nb = 0; nb < 4; nb++) {
            uint32_t bk[4];
            ldm_x4(bk, aKH + ((n0 + nb * 16 + lr) * PITCH + col) * 2);
            mma_f16(acc[0][2 * nb],     a0, bk[0], bk[2]);
            mma_f16(acc[0][2 * nb + 1], a0, bk[1], bk[3]);
            mma_f16(acc[1][2 * nb],     a1, bk[0], bk[2]);
            mma_f16(acc[1][2 * nb + 1], a1, bk[1], bk[3]);
        }
    }

    // epilogue: E = ex2(s*C - 4); fragment-direct coalesced stores + colsums
    const float C = 0.18033688f;
    uint2* Ew = (uint2*)(g_E + (size_t)buf * ECH) +
                ((((size_t)zb * 16 + qt) * 16 + kt) * 8 + w) * 512;
    float csum[16];
    #pragma unroll
    for (int j = 0; j < 16; j++) csum[j] = 0.f;

    #pragma unroll
    for (int mi = 0; mi < 2; mi++) {
        #pragma unroll
        for (int j = 0; j < 8; j++) {
            float e0 = ex2f(fmaf(acc[mi][j][0], C, -4.0f));
            float e1 = ex2f(fmaf(acc[mi][j][1], C, -4.0f));
            float e2 = ex2f(fmaf(acc[mi][j][2], C, -4.0f));
            float e3 = ex2f(fmaf(acc[mi][j][3], C, -4.0f));
            __half2 hA = __floats2half2_rn(e0, e1);
            __half2 hB = __floats2half2_rn(e2, e3);
            Ew[(mi * 8 + j) * 32 + lane] = make_uint2(*(uint32_t*)&hA, *(uint32_t*)&hB);
            csum[2 * j]     += e0 + e2;
            csum[2 * j + 1] += e1 + e3;
        }
    }

    #pragma unroll
    for (int off = 4; off <= 16; off <<= 1) {
        #pragma unroll
        for (int j = 0; j < 16; j++)
            csum[j] += __shfl_xor_sync(0xffffffffu, csum[j], off);
    }
    if (lane < 4) {
        int tq = lane;
        float* zp = g_Z + b * NS + k0 + n0 + 2 * tq;
        #pragma unroll
        for (int j = 0; j < 8; j++) {
            atomicAdd(zp + j * 8,     csum[2 * j]);
            atomicAdd(zp + j * 8 + 1, csum[2 * j + 1]);
        }
    }
}

// ---------------- kernel 4: w = u / Z (chunk) -------------------------------------
__global__ void k_w(int b0) {
    int i = b0 * NS + blockIdx.x * 256 + threadIdx.x;
    g_w[i] = g_u[i] / g_Z[i];
}

// ---------------- kernel 5: out from fragment-blocked E ---------------------------
__global__ __launch_bounds__(256) void k_out(int b0, int buf,
                                             const float* __restrict__ bf,
                                             float* __restrict__ out) {
    __shared__ float ws[NS];
    int zb = blockIdx.y;
    int qt = blockIdx.x >> 2;
    int wm = blockIdx.x & 3;
    int b = b0 + zb;
    int t = threadIdx.x;

    const float4* wg = (const float4*)(g_w + b * NS);
    float4* wsm = (float4*)ws;
    #pragma unroll
    for (int i = 0; i < 2; i++) wsm[t + i * 256] = wg[t + i * 256];
    __syncthreads();

    int g = t >> 5, lane = t & 31;
    int mi = lane >> 4;
    int j = (lane >> 1) & 7;
    int tqp = lane & 1;

    int frag_off = (mi * 8 + j) * 32 + g * 4 + tqp * 2;
    const uint2* Eb = (const uint2*)(g_E + (size_t)buf * ECH) +
                      (((size_t)zb * 16 + qt) * 16) * 8 * 512;

    u64 accA = 0, accB = 0;
    #pragma unroll 4
    for (int it = 0; it < 32; it++) {
        int kt = it >> 1, wn = it & 1;
        const uint4* src = (const uint4*)(Eb + ((size_t)kt * 8 + wn * 4 + wm) * 512 + frag_off);
        uint4 v = *src;
        const float4 w4 = *(const float4*)(ws + kt * 128 + wn * 64 + j * 8 + tqp * 4);
        float2 f0 = __half22float2(*(__half2*)&v.x);
        float2 f1 = __half22float2(*(__half2*)&v.y);
        float2 f2 = __half22float2(*(__half2*)&v.z);
        float2 f3 = __half22float2(*(__half2*)&v.w);
        fma2(accA, pack2(f0.x, f0.y), pack2(w4.x, w4.y));
        fma2(accA, pack2(f2.x, f2.y), pack2(w4.z, w4.w));
        fma2(accB, pack2(f1.x, f1.y), pack2(w4.x, w4.y));
        fma2(accB, pack2(f3.x, f3.y), pack2(w4.z, w4.w));
    }
    float2 pA = unpack2(accA), pB = unpack2(accB);
    float sA = pA.x + pA.y;
    float sB = pB.x + pB.y;
    #pragma unroll
    for (int off = 1; off <= 8; off <<= 1) {
        sA += __shfl_xor_sync(0xffffffffu, sA, off);
        sB += __shfl_xor_sync(0xffffffffu, sB, off);
    }
    if ((lane & 15) == 0) {
        int rA = qt * 128 + wm * 32 + mi * 16 + g;
        float bias = bf[0];
        out[b * NS + rA]     = sA + bias;
        out[b * NS + rA + 8] = sB + bias;
    }
}

// ---------------- host launcher: dual-stream chunk pipeline -----------------------
extern "C" void kernel_launch(void* const* d_in, const int* in_sizes, int n_in,
                              void* d_out, int out_size) {
    (void)in_sizes; (void)n_in; (void)out_size;
    const float* x  = (const float*)d_in[0];
    const float* Wq = (const float*)d_in[1];
    const float* Wk = (const float*)d_in[2];
    const float* Wv = (const float*)d_in[3];
    const float* Wf = (const float*)d_in[4];
    const float* bf = (const float*)d_in[5];
    float* out = (float*)d_out;

    cudaFuncSetAttribute(k_qk,     cudaFuncAttributeMaxDynamicSharedMemorySize, 65536);
    cudaFuncSetAttribute(k_scores, cudaFuncAttributeMaxDynamicSharedMemorySize, 36864);

    // side stream + fork/join events (created per call; capture-safe, leaked)
    cudaStream_t s1;
    cudaStreamCreateWithFlags(&s1, cudaStreamNonBlocking);
    cudaEvent_t ev0, ev1, evF;
    cudaEventCreateWithFlags(&ev0, cudaEventDisableTiming);
    cudaEventCreateWithFlags(&ev1, cudaEventDisableTiming);
    cudaEventCreateWithFlags(&evF, cudaEventDisableTiming);

    dim3 sg(16, 16, CB);   // (k-tiles, q-tiles, chunk batches)
    dim3 og(64, CB);       // (qt*4+wm, zb)

    k_pewvf<<<NS / 4, 256>>>(Wv, Wf);
    k_qk<<<(NB * NS) / 128, 512, 65536>>>(x, Wq, Wk);

    k_scores<<<sg, 256, 36864>>>(0, 0);
    k_w<<<(CB * NS) / 256, 256>>>(0);
    cudaEventRecord(ev0, 0);

    k_scores<<<sg, 256, 36864>>>(CB, 1);
    k_w<<<(CB * NS) / 256, 256>>>(CB);
    cudaEventRecord(ev1, 0);

    cudaStreamWaitEvent(s1, ev0, 0);
    k_out<<<og, 256, 0, s1>>>(0, 0, bf, out);       // overlaps k_scores(chunk 1)
    cudaStreamWaitEvent(s1, ev1, 0);
    k_out<<<og, 256, 0, s1>>>(CB, 1, bf, out);

    cudaEventRecord(evF, s1);
    cudaStreamWaitEvent(0, evF, 0);                 // join back to capture stream
}

// round 14
// speedup vs baseline: 1.0259x; 1.0259x over previous
#include <cuda_runtime.h>
#include <cuda_fp16.h>
#include <math.h>
#include <stdint.h>

#define NB 16
#define NS 2048
#define NH 128
#define ND 64
#define CB 8          // batches per chunk (E kept L2-resident per chunk)

typedef unsigned long long u64;

// ---------------- scratch (device globals; no allocation allowed) ----------------
__device__ float g_pe[NS * NH];
__device__ __half g_Qh[NB * NS * ND];           // fp16 Q
__device__ __half g_Kh[NB * NS * ND];           // fp16 K
__device__ float g_wvf[NH];
__device__ float g_u[NB * NS];
__device__ float g_Z[NB * NS];
__device__ float g_w[NB * NS];
__device__ int   g_cnt[NB];                     // per-batch CTA completion counters (self-resetting)
// E chunk in FRAGMENT-BLOCKED layout (written by k_scores, read only by k_out):
// uint2 index = ((((zb*16+qt)*16+kt)*8 + warp)*16 + mi*8+j)*32 + lane
__device__ __half g_E[(size_t)CB * NS * NS];    // 67 MB (L2-resident, reused)

// ---------------- helpers ---------------------------------------------------------
__device__ __forceinline__ uint32_t smem_u32(const void* p) {
    uint32_t a;
    asm("{ .reg .u64 t; cvta.to.shared.u64 t, %1; cvt.u32.u64 %0, t; }" : "=r"(a) : "l"(p));
    return a;
}
__device__ __forceinline__ void ldm_x4(uint32_t* r, uint32_t addr) {
    asm volatile("ldmatrix.sync.aligned.m8n8.x4.shared.b16 {%0,%1,%2,%3}, [%4];"
                 : "=r"(r[0]), "=r"(r[1]), "=r"(r[2]), "=r"(r[3]) : "r"(addr));
}
__device__ __forceinline__ void mma_f16(float* c, const uint32_t* a,
                                        uint32_t b0, uint32_t b1) {
    asm volatile(
        "mma.sync.aligned.m16n8k16.row.col.f32.f16.f16.f32 "
        "{%0,%1,%2,%3}, {%4,%5,%6,%7}, {%8,%9}, {%0,%1,%2,%3};"
        : "+f"(c[0]), "+f"(c[1]), "+f"(c[2]), "+f"(c[3])
        : "r"(a[0]), "r"(a[1]), "r"(a[2]), "r"(a[3]), "r"(b0), "r"(b1));
}
__device__ __forceinline__ float ex2f(float v) {
    float r; asm("ex2.approx.ftz.f32 %0, %1;" : "=f"(r) : "f"(v)); return r;
}
__device__ __forceinline__ u64 pack2(float lo, float hi) {
    u64 r; asm("mov.b64 %0, {%1,%2};" : "=l"(r) : "f"(lo), "f"(hi)); return r;
}
__device__ __forceinline__ void fma2(u64& c, u64 a, u64 b) {
    asm("fma.rn.f32x2 %0, %1, %2, %0;" : "+l"(c) : "l"(a), "l"(b));
}
__device__ __forceinline__ float2 unpack2(u64 v) {
    float lo, hi; asm("mov.b64 {%0,%1}, %2;" : "=f"(lo), "=f"(hi) : "l"(v));
    return make_float2(lo, hi);
}

// ---------------- kernel 1: sinusoidal PE + wvf (merged) --------------------------
__global__ void k_pewvf(const float* __restrict__ Wv, const float* __restrict__ Wf) {
    int t = threadIdx.x;
    int p = blockIdx.x * 4 + (t >> 6);
    int i = t & 63;
    double inv_rate = exp2(-(double)i * 0.20762050593046016);  // 10000^(-i/64)
    double ang = (double)p * inv_rate;
    double k = rint(ang * 0.15915494309189535);
    double r = fma(-k, 6.283185307179586, ang);
    r = fma(-k, 2.4492935982947064e-16, r);
    float s, c;
    sincosf((float)r, &s, &c);
    g_pe[p * NH + 2 * i]     = s;
    g_pe[p * NH + 2 * i + 1] = c;

    if (blockIdx.x == 0 && t < 128) {
        float sum = 0.f;
        #pragma unroll 8
        for (int d = 0; d < ND; d++) sum += Wv[t * ND + d] * Wf[d];
        g_wvf[t] = sum;
    }
}

// ---------------- kernel 2: fused xp=x+pe -> {Q,K} fp16 (HMMA) + u + Z=0 ----------
__global__ __launch_bounds__(512, 2) void k_qk(const float* __restrict__ x,
                                               const float* __restrict__ Wq,
                                               const float* __restrict__ Wk) {
    extern __shared__ __align__(16) char qs[];
    char* XPs = qs;             // [128 rows][256 B]
    char* Ws  = qs + 32768;     // [128 n][256 B]
    int t = threadIdx.x;
    int w = t >> 5, lane = t & 31;
    int r0 = blockIdx.x * 128;
    int s0 = r0 & (NS - 1);

    int zi = blockIdx.x * 512 + t;          // zero Z, bounds-guarded
    if (zi < NB * NS) g_Z[zi] = 0.f;

    // stage W transposed to [n][k] fp16
    #pragma unroll
    for (int i = 0; i < 4; i++) {
        int id = t + i * 512;
        int n = id & 127, o = id >> 7;
        const float* src = (n < 64) ? (Wq + n) : (Wk + (n - 64));
        float v0 = src[(8 * o + 0) * 64], v1 = src[(8 * o + 1) * 64];
        float v2 = src[(8 * o + 2) * 64], v3 = src[(8 * o + 3) * 64];
        float v4 = src[(8 * o + 4) * 64], v5 = src[(8 * o + 5) * 64];
        float v6 = src[(8 * o + 6) * 64], v7 = src[(8 * o + 7) * 64];
        __half2 h0 = __floats2half2_rn(v0, v1);
        __half2 h1 = __floats2half2_rn(v2, v3);
        __half2 h2 = __floats2half2_rn(v4, v5);
        __half2 h3 = __floats2half2_rn(v6, v7);
        int chunk = o ^ (n & 7);
        *(uint4*)(Ws + n * 256 + chunk * 16) =
            make_uint4(*(uint32_t*)&h0, *(uint32_t*)&h1, *(uint32_t*)&h2, *(uint32_t*)&h3);
    }

    // stage XP (fp16) + u (fp32)
    float4 wv = ((const float4*)g_wvf)[lane];
    #pragma unroll
    for (int i = 0; i < 8; i++) {
        int row = w + 16 * i;
        float4 xv = ((const float4*)(x    + (size_t)(r0 + row) * NH))[lane];
        float4 pv = ((const float4*)(g_pe + (size_t)(s0 + row) * NH))[lane];
        float xpx = xv.x + pv.x, xpy = xv.y + pv.y;
        float xpz = xv.z + pv.z, xpw = xv.w + pv.w;
        float up = xpx * wv.x + xpy * wv.y + xpz * wv.z + xpw * wv.w;
        #pragma unroll
        for (int off = 16; off; off >>= 1) up += __shfl_down_sync(0xffffffffu, up, off);
        if (lane == 0) g_u[r0 + row] = up;
        __half2 hA = __floats2half2_rn(xpx, xpy);
        __half2 hB = __floats2half2_rn(xpz, xpw);
        int chunk = (lane >> 1) ^ (row & 7);
        *(uint2*)(XPs + row * 256 + chunk * 16 + (lane & 1) * 8) =
            make_uint2(*(uint32_t*)&hA, *(uint32_t*)&hB);
    }
    __syncthreads();

    // mma: 16 warps = 8 warp_m x 2 warp_n; warp tile 16 rows x 64 cols
    int warp_m = w >> 1, warp_n = w & 1;
    int m0 = warp_m * 16, nb0 = warp_n * 64;
    int lr = lane & 15, lch = lane >> 4;

    uint32_t aXP = smem_u32(XPs), aW = smem_u32(Ws);
    float acc[8][4] = {};
    #pragma unroll
    for (int ks = 0; ks < 8; ks++) {
        uint32_t a[4];
        int rowA = m0 + lr;
        ldm_x4(a, aXP + rowA * 256 + (((2 * ks + lch) ^ (rowA & 7)) << 4));
        #pragma unroll
        for (int nb = 0; nb < 4; nb++) {
            int rowB = nb0 + nb * 16 + lr;
            uint32_t bk[4];
            ldm_x4(bk, aW + rowB * 256 + (((2 * ks + lch) ^ (rowB & 7)) << 4));
            mma_f16(acc[2 * nb],     a, bk[0], bk[2]);
            mma_f16(acc[2 * nb + 1], a, bk[1], bk[3]);
        }
    }

    int g = lane >> 2, tq = lane & 3;
    __half* base = warp_n ? g_Kh : g_Qh;
    #pragma unroll
    for (int mi = 0; mi < 2; mi++) {
        __half* drow = base + (size_t)(r0 + m0 + 8 * mi + g) * ND;
        #pragma unroll
        for (int nb = 0; nb < 4; nb++) {
            #pragma unroll
            for (int jj = 0; jj < 2; jj++) {
                int col = nb * 16 + jj * 8 + 2 * tq;
                __half2 hv = __floats2half2_rn(acc[2 * nb + jj][2 * mi],
                                               acc[2 * nb + jj][2 * mi + 1]);
                *(uint32_t*)(drow + col) = *(uint32_t*)&hv;
            }
        }
    }
}

// ---------------- kernel 3: E = exp(QK^T/8)/16 -> fragment-blocked gmem -----------
// Tail: last CTA per batch (counter + threadfence) computes w = u/Z for that batch
// and resets the counter (graph-replay safe). Deletes the k_w kernel nodes.
__global__ __launch_bounds__(256, 2) void k_scores(int b0) {
    extern __shared__ __align__(16) __half smh[];
    const int PITCH = 72;
    __half* QH = smh;                     // [128][72]
    __half* KH = smh + 128 * PITCH;
    __shared__ int s_last;

    int t = threadIdx.x;
    int w = t >> 5, lane = t & 31;
    int zb = blockIdx.z;                  // 0..CB-1 (E index)
    int b = b0 + zb;                      // global batch
    int qt = blockIdx.y;
    int kt = blockIdx.x;
    int k0 = kt * 128;

    const uint4* Qg = (const uint4*)(g_Qh + ((size_t)b * NS + qt * 128) * ND);
    const uint4* Kg = (const uint4*)(g_Kh + ((size_t)b * NS + k0) * ND);
    #pragma unroll
    for (int i = 0; i < 4; i++) {
        int e = t + i * 256;
        int r = e >> 3, c8 = e & 7;
        int off = r * PITCH + c8 * 8;
        *(uint4*)(QH + off) = Qg[e];
        *(uint4*)(KH + off) = Kg[e];
    }
    __syncthreads();

    int warp_m = w & 3, warp_n = w >> 2;
    int m0 = warp_m * 32, n0 = warp_n * 64;
    int lr = lane & 15;
    int lc = (lane >> 4) << 3;

    uint32_t aQH = smem_u32(QH), aKH = smem_u32(KH);
    float acc[2][8][4] = {};

    #pragma unroll
    for (int ks = 0; ks < 4; ks++) {
        int col = ks * 16 + lc;
        uint32_t a0[4], a1[4];
        ldm_x4(a0, aQH + ((m0 + lr) * PITCH + col) * 2);
        ldm_x4(a1, aQH + ((m0 + 16 + lr) * PITCH + col) * 2);
        #pragma unroll
        for (int nb = 0; nb < 4; nb++) {
            uint32_t bk[4];
            ldm_x4(bk, aKH + ((n0 + nb * 16 + lr) * PITCH + col) * 2);
            mma_f16(acc[0][2 * nb],     a0, bk[0], bk[2]);
            mma_f16(acc[0][2 * nb + 1], a0, bk[1], bk[3]);
            mma_f16(acc[1][2 * nb],     a1, bk[0], bk[2]);
            mma_f16(acc[1][2 * nb + 1], a1, bk[1], bk[3]);
        }
    }

    // epilogue: E = ex2(s*C - 4); fragment-direct coalesced stores + colsums
    const float C = 0.18033688f;
    uint2* Ew = (uint2*)g_E + ((((size_t)zb * 16 + qt) * 16 + kt) * 8 + w) * 512;
    float csum[16];
    #pragma unroll
    for (int j = 0; j < 16; j++) csum[j] = 0.f;

    #pragma unroll
    for (int mi = 0; mi < 2; mi++) {
        #pragma unroll
        for (int j = 0; j < 8; j++) {
            float e0 = ex2f(fmaf(acc[mi][j][0], C, -4.0f));
            float e1 = ex2f(fmaf(acc[mi][j][1], C, -4.0f));
            float e2 = ex2f(fmaf(acc[mi][j][2], C, -4.0f));
            float e3 = ex2f(fmaf(acc[mi][j][3], C, -4.0f));
            __half2 hA = __floats2half2_rn(e0, e1);
            __half2 hB = __floats2half2_rn(e2, e3);
            Ew[(mi * 8 + j) * 32 + lane] = make_uint2(*(uint32_t*)&hA, *(uint32_t*)&hB);
            csum[2 * j]     += e0 + e2;
            csum[2 * j + 1] += e1 + e3;
        }
    }

    #pragma unroll
    for (int off = 4; off <= 16; off <<= 1) {
        #pragma unroll
        for (int j = 0; j < 16; j++)
            csum[j] += __shfl_xor_sync(0xffffffffu, csum[j], off);
    }
    if (lane < 4) {
        int tq = lane;
        float* zp = g_Z + b * NS + k0 + n0 + 2 * tq;
        #pragma unroll
        for (int j = 0; j < 8; j++) {
            atomicAdd(zp + j * 8,     csum[2 * j]);
            atomicAdd(zp + j * 8 + 1, csum[2 * j + 1]);
        }
    }

    // ---- last-CTA-per-batch tail: w = u / Z --------------------------------------
    __threadfence();                      // order this thread's Z atomics globally
    __syncthreads();                      // all threads' fences done
    if (t == 0) {
        int old = atomicAdd(&g_cnt[b], 1);
        s_last = (old == 255);            // 16x16 = 256 CTAs per batch
    }
    __syncthreads();
    if (s_last) {
        #pragma unroll
        for (int i = 0; i < 8; i++) {
            int k = t + i * 256;
            float z = __ldcg(&g_Z[b * NS + k]);   // L2 read (atomics live in L2)
            g_w[b * NS + k] = g_u[b * NS + k] / z;
        }
        if (t == 0) g_cnt[b] = 0;         // reset for next graph replay
    }
}

// ---------------- kernel 4: out from fragment-blocked E ---------------------------
__global__ __launch_bounds__(256) void k_out(int b0, const float* __restrict__ bf,
                                             float* __restrict__ out) {
    __shared__ float ws[NS];
    int zb = blockIdx.y;
    int qt = blockIdx.x >> 2;
    int wm = blockIdx.x & 3;
    int b = b0 + zb;
    int t = threadIdx.x;

    const float4* wg = (const float4*)(g_w + b * NS);
    float4* wsm = (float4*)ws;
    #pragma unroll
    for (int i = 0; i < 2; i++) wsm[t + i * 256] = wg[t + i * 256];
    __syncthreads();

    int g = t >> 5, lane = t & 31;
    int mi = lane >> 4;
    int j = (lane >> 1) & 7;
    int tqp = lane & 1;

    int frag_off = (mi * 8 + j) * 32 + g * 4 + tqp * 2;
    const uint2* Eb = (const uint2*)g_E + (((size_t)zb * 16 + qt) * 16) * 8 * 512;

    u64 accA = 0, accB = 0;
    #pragma unroll 4
    for (int it = 0; it < 32; it++) {
        int kt = it >> 1, wn = it & 1;
        const uint4* src = (const uint4*)(Eb + ((size_t)kt * 8 + wn * 4 + wm) * 512 + frag_off);
        uint4 v = *src;
        const float4 w4 = *(const float4*)(ws + kt * 128 + wn * 64 + j * 8 + tqp * 4);
        float2 f0 = __half22float2(*(__half2*)&v.x);
        float2 f1 = __half22float2(*(__half2*)&v.y);
        float2 f2 = __half22float2(*(__half2*)&v.z);
        float2 f3 = __half22float2(*(__half2*)&v.w);
        fma2(accA, pack2(f0.x, f0.y), pack2(w4.x, w4.y));
        fma2(accA, pack2(f2.x, f2.y), pack2(w4.z, w4.w));
        fma2(accB, pack2(f1.x, f1.y), pack2(w4.x, w4.y));
        fma2(accB, pack2(f3.x, f3.y), pack2(w4.z, w4.w));
    }
    float2 pA = unpack2(accA), pB = unpack2(accB);
    float sA = pA.x + pA.y;
    float sB = pB.x + pB.y;
    #pragma unroll
    for (int off = 1; off <= 8; off <<= 1) {
        sA += __shfl_xor_sync(0xffffffffu, sA, off);
        sB += __shfl_xor_sync(0xffffffffu, sB, off);
    }
    if ((lane & 15) == 0) {
        int rA = qt * 128 + wm * 32 + mi * 16 + g;
        float bias = bf[0];
        out[b * NS + rA]     = sA + bias;
        out[b * NS + rA + 8] = sB + bias;
    }
}

// ---------------- host launcher: 6 graph nodes, single stream ---------------------
extern "C" void kernel_launch(void* const* d_in, const int* in_sizes, int n_in,
                              void* d_out, int out_size) {
    (void)in_sizes; (void)n_in; (void)out_size;
    const float* x  = (const float*)d_in[0];
    const float* Wq = (const float*)d_in[1];
    const float* Wk = (const float*)d_in[2];
    const float* Wv = (const float*)d_in[3];
    const float* Wf = (const float*)d_in[4];
    const float* bf = (const float*)d_in[5];
    float* out = (float*)d_out;

    cudaFuncSetAttribute(k_qk,     cudaFuncAttributeMaxDynamicSharedMemorySize, 65536);
    cudaFuncSetAttribute(k_scores, cudaFuncAttributeMaxDynamicSharedMemorySize, 36864);

    k_pewvf<<<NS / 4, 256>>>(Wv, Wf);
    k_qk<<<(NB * NS) / 128, 512, 65536>>>(x, Wq, Wk);

    for (int c = 0; c < NB / CB; c++) {
        int b0 = c * CB;
        dim3 sg(16, 16, CB);   // (k-tiles, q-tiles, chunk batches)
        k_scores<<<sg, 256, 36864>>>(b0);
        dim3 og(64, CB);       // (qt*4+wm, zb)
        k_out<<<og, 256>>>(b0, bf, out);
    }
}

// round 17
// speedup vs baseline: 1.2103x; 1.1798x over previous
#include <cuda_runtime.h>
#include <cuda_fp16.h>
#include <math.h>
#include <stdint.h>

#define NB 16
#define NS 2048
#define NH 128
#define ND 64
#define CB 8          // batches per chunk (E kept L2-resident per chunk)

typedef unsigned long long u64;

// ---------------- scratch (device globals; no allocation allowed) ----------------
__device__ float g_pe[NS * NH];
__device__ __half g_Qh[NB * NS * ND];           // fp16 Q
__device__ __half g_Kh[NB * NS * ND];           // fp16 K
__device__ float g_wvf[NH];
__device__ float g_u[NB * NS];
__device__ float g_Z[NB * NS];
__device__ float g_w[NB * NS];
// E chunk in FRAGMENT-BLOCKED layout (written by k_scores, read only by k_out):
// uint2 index = ((((zb*16+qt)*16+kt)*8 + warp)*16 + mi*8+j)*32 + lane
__device__ __half g_E[(size_t)CB * NS * NS];    // 67 MB (pinned in L2 via evict_last policy)

// ---------------- helpers ---------------------------------------------------------
__device__ __forceinline__ uint32_t smem_u32(const void* p) {
    uint32_t a;
    asm("{ .reg .u64 t; cvta.to.shared.u64 t, %1; cvt.u32.u64 %0, t; }" : "=r"(a) : "l"(p));
    return a;
}
__device__ __forceinline__ void ldm_x4(uint32_t* r, uint32_t addr) {
    asm volatile("ldmatrix.sync.aligned.m8n8.x4.shared.b16 {%0,%1,%2,%3}, [%4];"
                 : "=r"(r[0]), "=r"(r[1]), "=r"(r[2]), "=r"(r[3]) : "r"(addr));
}
__device__ __forceinline__ void mma_f16(float* c, const uint32_t* a,
                                        uint32_t b0, uint32_t b1) {
    asm volatile(
        "mma.sync.aligned.m16n8k16.row.col.f32.f16.f16.f32 "
        "{%0,%1,%2,%3}, {%4,%5,%6,%7}, {%8,%9}, {%0,%1,%2,%3};"
        : "+f"(c[0]), "+f"(c[1]), "+f"(c[2]), "+f"(c[3])
        : "r"(a[0]), "r"(a[1]), "r"(a[2]), "r"(a[3]), "r"(b0), "r"(b1));
}
__device__ __forceinline__ float ex2f(float v) {
    float r; asm("ex2.approx.ftz.f32 %0, %1;" : "=f"(r) : "f"(v)); return r;
}
__device__ __forceinline__ u64 pack2(float lo, float hi) {
    u64 r; asm("mov.b64 %0, {%1,%2};" : "=l"(r) : "f"(lo), "f"(hi)); return r;
}
__device__ __forceinline__ void fma2(u64& c, u64 a, u64 b) {
    asm("fma.rn.f32x2 %0, %1, %2, %0;" : "+l"(c) : "l"(a), "l"(b));
}
__device__ __forceinline__ float2 unpack2(u64 v) {
    float lo, hi; asm("mov.b64 {%0,%1}, %2;" : "=f"(lo), "=f"(hi) : "l"(v));
    return make_float2(lo, hi);
}
// L2 eviction policies via createpolicy + cache_hint (no vector-width restriction)
__device__ __forceinline__ u64 policy_evict_last() {
    u64 p; asm("createpolicy.fractional.L2::evict_last.b64 %0, 1.0;" : "=l"(p));
    return p;
}
__device__ __forceinline__ u64 policy_evict_first() {
    u64 p; asm("createpolicy.fractional.L2::evict_first.b64 %0, 1.0;" : "=l"(p));
    return p;
}
__device__ __forceinline__ void st_evl(void* p, uint32_t a, uint32_t b, u64 pol) {
    asm volatile("st.global.L2::cache_hint.v2.u32 [%0], {%1,%2}, %3;"
                 :: "l"(p), "r"(a), "r"(b), "l"(pol) : "memory");
}
__device__ __forceinline__ uint4 ld_evf(const void* p, u64 pol) {
    uint4 v;
    asm volatile("ld.global.nc.L2::cache_hint.v4.u32 {%0,%1,%2,%3}, [%4], %5;"
                 : "=r"(v.x), "=r"(v.y), "=r"(v.z), "=r"(v.w) : "l"(p), "l"(pol));
    return v;
}

// ---------------- kernel 1: sinusoidal PE + wvf (merged) --------------------------
__global__ void k_pewvf(const float* __restrict__ Wv, const float* __restrict__ Wf) {
    int t = threadIdx.x;
    int p = blockIdx.x * 4 + (t >> 6);
    int i = t & 63;
    double inv_rate = exp2(-(double)i * 0.20762050593046016);  // 10000^(-i/64)
    double ang = (double)p * inv_rate;
    double k = rint(ang * 0.15915494309189535);
    double r = fma(-k, 6.283185307179586, ang);
    r = fma(-k, 2.4492935982947064e-16, r);
    float s, c;
    sincosf((float)r, &s, &c);
    g_pe[p * NH + 2 * i]     = s;
    g_pe[p * NH + 2 * i + 1] = c;

    if (blockIdx.x == 0 && t < 128) {
        float sum = 0.f;
        #pragma unroll 8
        for (int d = 0; d < ND; d++) sum += Wv[t * ND + d] * Wf[d];
        g_wvf[t] = sum;
    }
}

// ---------------- kernel 2: fused xp=x+pe -> {Q,K} fp16 (HMMA) + u + Z=0 ----------
__global__ __launch_bounds__(512, 2) void k_qk(const float* __restrict__ x,
                                               const float* __restrict__ Wq,
                                               const float* __restrict__ Wk) {
    extern __shared__ __align__(16) char qs[];
    char* XPs = qs;             // [128 rows][256 B]
    char* Ws  = qs + 32768;     // [128 n][256 B]
    int t = threadIdx.x;
    int w = t >> 5, lane = t & 31;
    int r0 = blockIdx.x * 128;
    int s0 = r0 & (NS - 1);

    int zi = blockIdx.x * 512 + t;          // zero Z, bounds-guarded
    if (zi < NB * NS) g_Z[zi] = 0.f;

    // stage W transposed to [n][k] fp16
    #pragma unroll
    for (int i = 0; i < 4; i++) {
        int id = t + i * 512;
        int n = id & 127, o = id >> 7;
        const float* src = (n < 64) ? (Wq + n) : (Wk + (n - 64));
        float v0 = src[(8 * o + 0) * 64], v1 = src[(8 * o + 1) * 64];
        float v2 = src[(8 * o + 2) * 64], v3 = src[(8 * o + 3) * 64];
        float v4 = src[(8 * o + 4) * 64], v5 = src[(8 * o + 5) * 64];
        float v6 = src[(8 * o + 6) * 64], v7 = src[(8 * o + 7) * 64];
        __half2 h0 = __floats2half2_rn(v0, v1);
        __half2 h1 = __floats2half2_rn(v2, v3);
        __half2 h2 = __floats2half2_rn(v4, v5);
        __half2 h3 = __floats2half2_rn(v6, v7);
        int chunk = o ^ (n & 7);
        *(uint4*)(Ws + n * 256 + chunk * 16) =
            make_uint4(*(uint32_t*)&h0, *(uint32_t*)&h1, *(uint32_t*)&h2, *(uint32_t*)&h3);
    }

    // stage XP (fp16) + u (fp32)
    float4 wv = ((const float4*)g_wvf)[lane];
    #pragma unroll
    for (int i = 0; i < 8; i++) {
        int row = w + 16 * i;
        float4 xv = ((const float4*)(x    + (size_t)(r0 + row) * NH))[lane];
        float4 pv = ((const float4*)(g_pe + (size_t)(s0 + row) * NH))[lane];
        float xpx = xv.x + pv.x, xpy = xv.y + pv.y;
        float xpz = xv.z + pv.z, xpw = xv.w + pv.w;
        float up = xpx * wv.x + xpy * wv.y + xpz * wv.z + xpw * wv.w;
        #pragma unroll
        for (int off = 16; off; off >>= 1) up += __shfl_down_sync(0xffffffffu, up, off);
        if (lane == 0) g_u[r0 + row] = up;
        __half2 hA = __floats2half2_rn(xpx, xpy);
        __half2 hB = __floats2half2_rn(xpz, xpw);
        int chunk = (lane >> 1) ^ (row & 7);
        *(uint2*)(XPs + row * 256 + chunk * 16 + (lane & 1) * 8) =
            make_uint2(*(uint32_t*)&hA, *(uint32_t*)&hB);
    }
    __syncthreads();

    // mma: 16 warps = 8 warp_m x 2 warp_n; warp tile 16 rows x 64 cols
    int warp_m = w >> 1, warp_n = w & 1;
    int m0 = warp_m * 16, nb0 = warp_n * 64;
    int lr = lane & 15, lch = lane >> 4;

    uint32_t aXP = smem_u32(XPs), aW = smem_u32(Ws);
    float acc[8][4] = {};
    #pragma unroll
    for (int ks = 0; ks < 8; ks++) {
        uint32_t a[4];
        int rowA = m0 + lr;
        ldm_x4(a, aXP + rowA * 256 + (((2 * ks + lch) ^ (rowA & 7)) << 4));
        #pragma unroll
        for (int nb = 0; nb < 4; nb++) {
            int rowB = nb0 + nb * 16 + lr;
            uint32_t bk[4];
            ldm_x4(bk, aW + rowB * 256 + (((2 * ks + lch) ^ (rowB & 7)) << 4));
            mma_f16(acc[2 * nb],     a, bk[0], bk[2]);
            mma_f16(acc[2 * nb + 1], a, bk[1], bk[3]);
        }
    }

    int g = lane >> 2, tq = lane & 3;
    __half* base = warp_n ? g_Kh : g_Qh;
    #pragma unroll
    for (int mi = 0; mi < 2; mi++) {
        __half* drow = base + (size_t)(r0 + m0 + 8 * mi + g) * ND;
        #pragma unroll
        for (int nb = 0; nb < 4; nb++) {
            #pragma unroll
            for (int jj = 0; jj < 2; jj++) {
                int col = nb * 16 + jj * 8 + 2 * tq;
                __half2 hv = __floats2half2_rn(acc[2 * nb + jj][2 * mi],
                                               acc[2 * nb + jj][2 * mi + 1]);
                *(uint32_t*)(drow + col) = *(uint32_t*)&hv;
            }
        }
    }
}

// ---------------- kernel 3: E = exp(QK^T/8)/16 -> fragment-blocked gmem -----------
__global__ __launch_bounds__(256, 2) void k_scores(int b0) {
    extern __shared__ __align__(16) __half smh[];
    const int PITCH = 72;
    __half* QH = smh;                     // [128][72]
    __half* KH = smh + 128 * PITCH;

    int t = threadIdx.x;
    int w = t >> 5, lane = t & 31;
    int zb = blockIdx.z;                  // 0..CB-1 (E index)
    int b = b0 + zb;                      // global batch
    int qt = blockIdx.y;
    int kt = blockIdx.x;
    int k0 = kt * 128;

    const uint4* Qg = (const uint4*)(g_Qh + ((size_t)b * NS + qt * 128) * ND);
    const uint4* Kg = (const uint4*)(g_Kh + ((size_t)b * NS + k0) * ND);
    #pragma unroll
    for (int i = 0; i < 4; i++) {
        int e = t + i * 256;
        int r = e >> 3, c8 = e & 7;
        int off = r * PITCH + c8 * 8;
        *(uint4*)(QH + off) = Qg[e];
        *(uint4*)(KH + off) = Kg[e];
    }
    __syncthreads();

    int warp_m = w & 3, warp_n = w >> 2;
    int m0 = warp_m * 32, n0 = warp_n * 64;
    int lr = lane & 15;
    int lc = (lane >> 4) << 3;

    uint32_t aQH = smem_u32(QH), aKH = smem_u32(KH);
    float acc[2][8][4] = {};

    #pragma unroll
    for (int ks = 0; ks < 4; ks++) {
        int col = ks * 16 + lc;
        uint32_t a0[4], a1[4];
        ldm_x4(a0, aQH + ((m0 + lr) * PITCH + col) * 2);
        ldm_x4(a1, aQH + ((m0 + 16 + lr) * PITCH + col) * 2);
        #pragma unroll
        for (int nb = 0; nb < 4; nb++) {
            uint32_t bk[4];
            ldm_x4(bk, aKH + ((n0 + nb * 16 + lr) * PITCH + col) * 2);
            mma_f16(acc[0][2 * nb],     a0, bk[0], bk[2]);
            mma_f16(acc[0][2 * nb + 1], a0, bk[1], bk[3]);
            mma_f16(acc[1][2 * nb],     a1, bk[0], bk[2]);
            mma_f16(acc[1][2 * nb + 1], a1, bk[1], bk[3]);
        }
    }

    // epilogue: E = ex2(s*C - 4); fragment-direct stores (evict_last) + colsums
    const float C = 0.18033688f;
    u64 pol = policy_evict_last();
    uint2* Ew = (uint2*)g_E + ((((size_t)zb * 16 + qt) * 16 + kt) * 8 + w) * 512;
    float csum[16];
    #pragma unroll
    for (int j = 0; j < 16; j++) csum[j] = 0.f;

    #pragma unroll
    for (int mi = 0; mi < 2; mi++) {
        #pragma unroll
        for (int j = 0; j < 8; j++) {
            float e0 = ex2f(fmaf(acc[mi][j][0], C, -4.0f));
            float e1 = ex2f(fmaf(acc[mi][j][1], C, -4.0f));
            float e2 = ex2f(fmaf(acc[mi][j][2], C, -4.0f));
            float e3 = ex2f(fmaf(acc[mi][j][3], C, -4.0f));
            __half2 hA = __floats2half2_rn(e0, e1);
            __half2 hB = __floats2half2_rn(e2, e3);
            st_evl(Ew + (mi * 8 + j) * 32 + lane, *(uint32_t*)&hA, *(uint32_t*)&hB, pol);
            csum[2 * j]     += e0 + e2;
            csum[2 * j + 1] += e1 + e3;
        }
    }

    #pragma unroll
    for (int off = 4; off <= 16; off <<= 1) {
        #pragma unroll
        for (int j = 0; j < 16; j++)
            csum[j] += __shfl_xor_sync(0xffffffffu, csum[j], off);
    }
    if (lane < 4) {
        int tq = lane;
        float* zp = g_Z + b * NS + k0 + n0 + 2 * tq;
        #pragma unroll
        for (int j = 0; j < 8; j++) {
            atomicAdd(zp + j * 8,     csum[2 * j]);
            atomicAdd(zp + j * 8 + 1, csum[2 * j + 1]);
        }
    }
}

// ---------------- kernel 4: w = u / Z (chunk; 16K divisions total) ----------------
__global__ void k_w(int b0) {
    int i = b0 * NS + blockIdx.x * 256 + threadIdx.x;
    g_w[i] = g_u[i] / g_Z[i];
}

// ---------------- kernel 5: out from fragment-blocked E (L2-hit reads) ------------
__global__ __launch_bounds__(256) void k_out(int b0, const float* __restrict__ bf,
                                             float* __restrict__ out) {
    __shared__ float ws[NS];
    int zb = blockIdx.y;
    int qt = blockIdx.x >> 2;
    int wm = blockIdx.x & 3;
    int b = b0 + zb;
    int t = threadIdx.x;

    const float4* wg = (const float4*)(g_w + b * NS);
    float4* wsm = (float4*)ws;
    #pragma unroll
    for (int i = 0; i < 2; i++) wsm[t + i * 256] = wg[t + i * 256];
    __syncthreads();

    int g = t >> 5, lane = t & 31;
    int mi = lane >> 4;
    int j = (lane >> 1) & 7;
    int tqp = lane & 1;

    int frag_off = (mi * 8 + j) * 32 + g * 4 + tqp * 2;
    const uint2* Eb = (const uint2*)g_E + (((size_t)zb * 16 + qt) * 16) * 8 * 512;
    u64 pol = policy_evict_first();

    u64 accA = 0, accB = 0;
    #pragma unroll 4
    for (int it = 0; it < 32; it++) {
        int kt = it >> 1, wn = it & 1;
        uint4 v = ld_evf(Eb + ((size_t)kt * 8 + wn * 4 + wm) * 512 + frag_off, pol);
        const float4 w4 = *(const float4*)(ws + kt * 128 + wn * 64 + j * 8 + tqp * 4);
        float2 f0 = __half22float2(*(__half2*)&v.x);
        float2 f1 = __half22float2(*(__half2*)&v.y);
        float2 f2 = __half22float2(*(__half2*)&v.z);
        float2 f3 = __half22float2(*(__half2*)&v.w);
        fma2(accA, pack2(f0.x, f0.y), pack2(w4.x, w4.y));
        fma2(accA, pack2(f2.x, f2.y), pack2(w4.z, w4.w));
        fma2(accB, pack2(f1.x, f1.y), pack2(w4.x, w4.y));
        fma2(accB, pack2(f3.x, f3.y), pack2(w4.z, w4.w));
    }
    float2 pA = unpack2(accA), pB = unpack2(accB);
    float sA = pA.x + pA.y;
    float sB = pB.x + pB.y;
    #pragma unroll
    for (int off = 1; off <= 8; off <<= 1) {
        sA += __shfl_xor_sync(0xffffffffu, sA, off);
        sB += __shfl_xor_sync(0xffffffffu, sB, off);
    }
    if ((lane & 15) == 0) {
        int rA = qt * 128 + wm * 32 + mi * 16 + g;
        float bias = bf[0];
        out[b * NS + rA]     = sA + bias;
        out[b * NS + rA + 8] = sB + bias;
    }
}

// ---------------- host launcher: 8 graph nodes, single stream ---------------------
extern "C" void kernel_launch(void* const* d_in, const int* in_sizes, int n_in,
                              void* d_out, int out_size) {
    (void)in_sizes; (void)n_in; (void)out_size;
    const float* x  = (const float*)d_in[0];
    const float* Wq = (const float*)d_in[1];
    const float* Wk = (const float*)d_in[2];
    const float* Wv = (const float*)d_in[3];
    const float* Wf = (const float*)d_in[4];
    const float* bf = (const float*)d_in[5];
    float* out = (float*)d_out;

    cudaFuncSetAttribute(k_qk,     cudaFuncAttributeMaxDynamicSharedMemorySize, 65536);
    cudaFuncSetAttribute(k_scores, cudaFuncAttributeMaxDynamicSharedMemorySize, 36864);

    k_pewvf<<<NS / 4, 256>>>(Wv, Wf);
    k_qk<<<(NB * NS) / 128, 512, 65536>>>(x, Wq, Wk);

    for (int c = 0; c < NB / CB; c++) {
        int b0 = c * CB;
        dim3 sg(16, 16, CB);   // (k-tiles, q-tiles, chunk batches)
        k_scores<<<sg, 256, 36864>>>(b0);
        k_w<<<(CB * NS) / 256, 256>>>(b0);
        dim3 og(64, CB);       // (qt*4+wm, zb)
        k_out<<<og, 256>>>(b0, bf, out);
    }
}